// round 3
// baseline (speedup 1.0000x reference)
#include <cuda_runtime.h>
#include <cuda_bf16.h>
#include <cstdint>
#include <cstddef>

// ============================================================================
// BinConv2d: BN(train stats) -> sign -> conv3x3(64->64,pad1) -> +bias -> ReLU
//   x:[32,64,112,112] f32 -> out same shape f32.
// sm_103-safe path (harness compiles PTX at compute_103: NO tcgen05):
//   mma.sync.m16n8k16 bf16 implicit GEMM, register accumulators.
//   k_stats/k_final : per-channel BN scale/shift (deterministic)
//   k_binarize      : NCHW f32 -> padded NHWC bf16 sign, 16B-chunk rotation
//   k_wprep         : W -> exact B-fragment layout, hi/lo bf16 split
//   k_conv          : persistent, M=256 px tile, N=64, K=1152,
//                     ldmatrix A direct from halo, double-buffered bulk halos
// ============================================================================

#define N_IMG 32
#define HH    112
#define WW    112
#define HP    114
#define PIX   (HH*WW)            // 12544
#define NTILE 1568               // 32 n * 7 th * 7 tw  (16x16 px tiles)

#define B_BYTES    147456        // 18 half-taps * 4 ksteps * 4 jpairs * 32 lanes * 16B
#define HALO_BYTES 41472         // 18 rows * 18 px * 128B
#define OFF_B      0
#define OFF_H0     (OFF_B + B_BYTES)       // 147456
#define OFF_H1     (OFF_H0 + HALO_BYTES)   // 188928
#define OFF_MBAR   (OFF_H1 + HALO_BYTES)   // 230400
#define SMEM_TOTAL (OFF_MBAR + 16)         // 230416 (< 232448 opt-in max)

// ---- scratch (device globals; no runtime allocation) ----
__device__ __align__(1024) __nv_bfloat16 g_xb[(size_t)N_IMG*HP*HP*64]; // 53.2MB
__device__ __align__(1024) unsigned char g_B[B_BYTES];
__device__ float2 g_part[64*32];
__device__ float2 g_ss[64];

// ============================ PTX helpers ===================================
static __device__ __forceinline__ uint32_t smem_u32(const void* p) {
    uint32_t a;
    asm("{ .reg .u64 t; cvta.to.shared.u64 t, %1; cvt.u32.u64 %0, t; }"
        : "=r"(a) : "l"(p));
    return a;
}

#define MBAR_INIT(mbar, cnt) \
    asm volatile("mbarrier.init.shared.b64 [%0], %1;" :: "r"(mbar), "r"(cnt) : "memory")

#define MBAR_EXPECT_TX(mbar, bytes) \
    asm volatile("mbarrier.arrive.expect_tx.shared.b64 _, [%0], %1;" \
                 :: "r"(mbar), "r"(bytes) : "memory")

#define MBAR_WAIT(mbar, ph) do {                                            \
    asm volatile("{\n\t.reg .pred P;\n\t"                                   \
        "WL%=:\n\t"                                                         \
        "mbarrier.try_wait.parity.acquire.cta.shared::cta.b64 P, [%0], %1, 0x989680;\n\t" \
        "@P bra.uni WD%=;\n\t"                                              \
        "bra.uni WL%=;\n\t"                                                 \
        "WD%=:\n\t}"                                                        \
        :: "r"(mbar), "r"((unsigned)(ph)) : "memory");                      \
} while (0)

#define BULK_G2S(dst, src, size, mbar) \
    asm volatile("cp.async.bulk.shared::cta.global.mbarrier::complete_tx::bytes [%0], [%1], %2, [%3];" \
                 :: "r"(dst), "l"(src), "r"(size), "r"(mbar) : "memory")

#define LDSM_X4(r, addr) \
    asm volatile("ldmatrix.sync.aligned.m8n8.x4.shared.b16 {%0,%1,%2,%3}, [%4];" \
        : "=r"((r)[0]),"=r"((r)[1]),"=r"((r)[2]),"=r"((r)[3]) : "r"(addr))

#define LDS128(v0,v1,v2,v3,addr) \
    asm volatile("ld.shared.v4.b32 {%0,%1,%2,%3}, [%4];" \
        : "=r"(v0),"=r"(v1),"=r"(v2),"=r"(v3) : "r"(addr))

#define MMA4(d, a, b0, b1) \
    asm volatile("mma.sync.aligned.m16n8k16.row.col.f32.bf16.bf16.f32 " \
        "{%0,%1,%2,%3}, {%4,%5,%6,%7}, {%8,%9}, {%0,%1,%2,%3};" \
        : "+f"((d)[0]),"+f"((d)[1]),"+f"((d)[2]),"+f"((d)[3]) \
        : "r"((a)[0]),"r"((a)[1]),"r"((a)[2]),"r"((a)[3]), "r"(b0),"r"(b1))

// ============================ pre-pass kernels ==============================

__global__ void k_stats(const float* __restrict__ x) {
    int c = blockIdx.x, n = blockIdx.y;
    const float* p = x + ((size_t)(n*64 + c)) * PIX;
    float s = 0.f, q = 0.f;
    for (int i = threadIdx.x; i < PIX; i += 256) { float v = p[i]; s += v; q += v*v; }
    __shared__ float rs[256], rq[256];
    rs[threadIdx.x] = s; rq[threadIdx.x] = q;
    __syncthreads();
    for (int o = 128; o > 0; o >>= 1) {
        if (threadIdx.x < o) { rs[threadIdx.x] += rs[threadIdx.x+o]; rq[threadIdx.x] += rq[threadIdx.x+o]; }
        __syncthreads();
    }
    if (threadIdx.x == 0) g_part[c*32 + n] = make_float2(rs[0], rq[0]);
}

__global__ void k_final(const float* __restrict__ gamma, const float* __restrict__ beta) {
    int c = threadIdx.x;
    if (c >= 64) return;
    float s = 0.f, q = 0.f;
    for (int n = 0; n < 32; n++) { float2 p = g_part[c*32 + n]; s += p.x; q += p.y; }
    const float inv = 1.0f / (float)(32*PIX);
    float mean = s * inv;
    float var  = q * inv - mean*mean;     // biased var, matches reference
    float sc = gamma[c] / sqrtf(var + 1e-4f);
    g_ss[c] = make_float2(sc, beta[c] - mean*sc);
}

// NCHW f32 -> padded NHWC bf16 sign with per-pixel 16B-chunk rotation
// (chunk position = chunk ^ (wp&7)) for conflict-free ldmatrix later.
__global__ void k_binarize(const float* __restrict__ x) {
    int hp = blockIdx.x, n = blockIdx.y;
    uint32_t* dst = (uint32_t*)(g_xb + ((size_t)(n*HP + hp)) * HP * 64); // rows of 32 u32
    if (hp == 0 || hp == HP-1) {
        for (int i = threadIdx.x; i < HP*32; i += 256) dst[i] = 0u;
        return;
    }
    __shared__ float s[64][113];
    __shared__ float2 ss[64];
    if (threadIdx.x < 64) ss[threadIdx.x] = g_ss[threadIdx.x];
    int h = hp - 1;
    const float* src = x + ((size_t)n*64) * PIX + (size_t)h * WW;
    for (int i = threadIdx.x; i < 64*WW; i += 256) {
        int c = i / WW, w = i % WW;
        s[c][w] = src[(size_t)c * PIX + w];
    }
    __syncthreads();
    if (threadIdx.x < 64) { // zero border columns wp=0, wp=113
        int cp = threadIdx.x & 31;
        int wp = (threadIdx.x < 32) ? 0 : (HP-1);
        dst[wp*32 + cp] = 0u;
    }
    for (int i = threadIdx.x; i < WW*32; i += 256) {
        int w = i >> 5, cp = i & 31, c = cp*2;
        float2 p0 = ss[c], p1 = ss[c+1];
        float v0 = s[c][w]   * p0.x + p0.y;
        float v1 = s[c+1][w] * p1.x + p1.y;
        uint32_t u0 = v0 > 0.f ? 0x3F80u : (v0 < 0.f ? 0xBF80u : 0u);
        uint32_t u1 = v1 > 0.f ? 0x3F80u : (v1 < 0.f ? 0xBF80u : 0u);
        int wp = w + 1;
        int pos = (((cp>>2) ^ (wp & 7)) << 2) | (cp & 3);
        dst[wp*32 + pos] = u0 | (u1 << 16);
    }
}

// W [64o][64i][3][3] f32 -> B fragments for mma.m16n8k16 (row.col):
// layout g_B[ ((ht*4+kc)*4 + j)*512 + lane*16 ] = {nc=2j:u0,u1, nc=2j+1:u0,u1}
// ht = tap*2 + {0:hi,1:lo}; b0,b1: k=tig*2,+1; b2,b3: k=tig*2+8,+9; n=nc*8+gid.
__global__ void k_wprep(const float* __restrict__ Wt) {
    int idx = blockIdx.x * 256 + threadIdx.x;
    if (idx >= 9216) return;
    int lane = idx & 31, j = (idx>>5)&3, kc = (idx>>7)&3, ht = idx>>9;
    int tap = ht >> 1, half = ht & 1;
    int gid = lane >> 2, tig = lane & 3;
    uint32_t o4[4];
    #pragma unroll
    for (int s2 = 0; s2 < 2; s2++) {
        int n = (j*2 + s2)*8 + gid;
        #pragma unroll
        for (int p = 0; p < 2; p++) {
            uint32_t pr = 0;
            #pragma unroll
            for (int e = 0; e < 2; e++) {
                int kch = kc*16 + tig*2 + e + p*8;
                float w = Wt[((size_t)n*64 + kch)*9 + tap];
                __nv_bfloat16 hi = __float2bfloat16(w);
                __nv_bfloat16 v = half ? __float2bfloat16(w - __bfloat162float(hi)) : hi;
                unsigned short us = *(unsigned short*)&v;
                pr |= (uint32_t)us << (e*16);
            }
            o4[s2*2 + p] = pr;
        }
    }
    *(uint4*)(g_B + (size_t)(((ht*4 + kc)*4 + j)*512) + (size_t)lane*16)
        = make_uint4(o4[0], o4[1], o4[2], o4[3]);
}

// ============================ conv kernel ===================================

static __device__ __forceinline__ void issue_halo(int tile, uint32_t dst, uint32_t mbar) {
    int nimg = tile / 49, r = tile % 49;
    int h0 = (r / 7) * 16, w0 = (r % 7) * 16;
    MBAR_EXPECT_TX(mbar, (unsigned)HALO_BYTES);
    const char* src = (const char*)g_xb + ((size_t)((nimg*HP + h0) * HP + w0)) * 128;
    #pragma unroll
    for (int rr = 0; rr < 18; rr++)
        BULK_G2S(dst + rr*2304, src + (size_t)rr * HP * 128, 2304u, mbar);
}

__global__ void __launch_bounds__(256, 1)
k_conv(const float* __restrict__ bias, float* __restrict__ out) {
    extern __shared__ char smem[];
    const uint32_t sb = smem_u32(smem);
    const int tid = threadIdx.x, wid = tid >> 5, L = tid & 31;
    const int wm = wid >> 1, nh = wid & 1;       // 4 M-groups x 2 N-halves
    const int gid = L >> 2, tig = L & 3;
    const int mx  = L & 15;                      // lane's ldmatrix row (pixel col)
    const int chi = L >> 4;                      // k 16B-chunk half

    // B fragments -> smem (linear copy; already fragment-packed)
    {
        const uint4* gb = (const uint4*)g_B;
        uint4* sB = (uint4*)smem;
        for (int i = tid; i < B_BYTES/16; i += 256) sB[i] = gb[i];
    }
    if (tid == 0) { MBAR_INIT(sb + OFF_MBAR, 1); MBAR_INIT(sb + OFF_MBAR + 8, 1); }
    __syncthreads();

    // bias in registers (2 consecutive out-channels per ncl)
    float bs[4][2];
    #pragma unroll
    for (int ncl = 0; ncl < 4; ncl++) {
        int n = (nh*4 + ncl)*8 + tig*2;
        bs[ncl][0] = bias[n]; bs[ncl][1] = bias[n+1];
    }

    if (tid == 0 && blockIdx.x < NTILE)
        issue_halo(blockIdx.x, sb + OFF_H0, sb + OFF_MBAR);

    int ph0 = 0, ph1 = 0;
    int it = 0;
    for (int tile = blockIdx.x; tile < NTILE; tile += gridDim.x, it++) {
        const int buf = it & 1;
        const int ntile = tile + gridDim.x;
        if (tid == 0 && ntile < NTILE)
            issue_halo(ntile, sb + (buf ? OFF_H0 : OFF_H1), sb + OFF_MBAR + (buf ^ 1)*8);

        if (buf == 0) { MBAR_WAIT(sb + OFF_MBAR,     ph0); ph0 ^= 1; }
        else          { MBAR_WAIT(sb + OFF_MBAR + 8, ph1); ph1 ^= 1; }
        const uint32_t hbase = sb + (buf ? OFF_H1 : OFF_H0);

        float acc[4][4][4];
        #pragma unroll
        for (int f = 0; f < 4; f++)
            #pragma unroll
            for (int c = 0; c < 4; c++)
                #pragma unroll
                for (int q = 0; q < 4; q++) acc[f][c][q] = 0.f;

        #pragma unroll 1
        for (int t = 0; t < 9; t++) {
            const int ky = t / 3, kx = t - ky*3;
            const int rk = (mx + kx) & 7;                 // rotation key
            const uint32_t rowbase = hbase
                + (uint32_t)(((wm*4 + ky)*18 + mx + kx) * 128);
            #pragma unroll
            for (int kc = 0; kc < 4; kc++) {
                const uint32_t col = (uint32_t)(((((kc<<1) | chi) ^ rk)) << 4);
                uint32_t a[4][4];
                #pragma unroll
                for (int f = 0; f < 4; f++)
                    LDSM_X4(a[f], rowbase + (uint32_t)(f*2304) + col);
                #pragma unroll
                for (int half = 0; half < 2; half++) {
                    const uint32_t bb = sb
                        + (uint32_t)(((((t*2 + half)*4 + kc)*4) + nh*2) * 512)
                        + (uint32_t)(L << 4);
                    uint32_t b0x, b0y, b0z, b0w, b1x, b1y, b1z, b1w;
                    LDS128(b0x, b0y, b0z, b0w, bb);
                    LDS128(b1x, b1y, b1z, b1w, bb + 512);
                    #pragma unroll
                    for (int f = 0; f < 4; f++) {
                        MMA4(acc[f][0], a[f], b0x, b0y);
                        MMA4(acc[f][1], a[f], b0z, b0w);
                        MMA4(acc[f][2], a[f], b1x, b1y);
                        MMA4(acc[f][3], a[f], b1z, b1w);
                    }
                }
            }
        }
        __syncthreads();   // all warps done reading halo[buf] before its next refill

        // epilogue: bias + ReLU, direct stores (32B sectors along w)
        {
            const int nimg = tile / 49, r = tile % 49;
            const int h0 = (r / 7) * 16, w0 = (r % 7) * 16;
            #pragma unroll
            for (int f = 0; f < 4; f++) {
                const int h = h0 + wm*4 + f;
                #pragma unroll
                for (int ncl = 0; ncl < 4; ncl++) {
                    const int n = (nh*4 + ncl)*8 + tig*2;
                    float* p0 = out + ((size_t)(nimg*64 + n)) * PIX
                                    + (size_t)h * WW + w0;
                    float v0 = acc[f][ncl][0] + bs[ncl][0];
                    float v1 = acc[f][ncl][1] + bs[ncl][1];
                    float v2 = acc[f][ncl][2] + bs[ncl][0];
                    float v3 = acc[f][ncl][3] + bs[ncl][1];
                    p0[gid]           = v0 > 0.f ? v0 : 0.f;
                    p0[PIX + gid]     = v1 > 0.f ? v1 : 0.f;
                    p0[gid + 8]       = v2 > 0.f ? v2 : 0.f;
                    p0[PIX + gid + 8] = v3 > 0.f ? v3 : 0.f;
                }
            }
        }
    }
}

// ============================ launch ========================================
extern "C" void kernel_launch(void* const* d_in, const int* in_sizes, int n_in,
                              void* d_out, int out_size) {
    (void)in_sizes; (void)n_in; (void)out_size;
    const float* x     = (const float*)d_in[0];
    const float* gamma = (const float*)d_in[1];
    const float* beta  = (const float*)d_in[2];
    const float* Wt    = (const float*)d_in[3];
    const float* b     = (const float*)d_in[4];
    float* out = (float*)d_out;

    int sms = 148;
    cudaDeviceGetAttribute(&sms, cudaDevAttrMultiProcessorCount, 0);
    cudaFuncSetAttribute(k_conv, cudaFuncAttributeMaxDynamicSharedMemorySize, SMEM_TOTAL);

    k_stats<<<dim3(64, 32), 256>>>(x);
    k_final<<<1, 64>>>(gamma, beta);
    k_binarize<<<dim3(HP, N_IMG), 256>>>(x);
    k_wprep<<<(9216 + 255)/256, 256>>>(Wt);
    k_conv<<<sms, 256, SMEM_TOTAL>>>(b, out);
}

// round 4
// speedup vs baseline: 1.3494x; 1.3494x over previous
#include <cuda_runtime.h>
#include <cuda_bf16.h>
#include <cuda_fp16.h>
#include <cstdint>
#include <cstddef>

// ============================================================================
// BinConv2d: BN(train stats) -> sign -> conv3x3(64->64,pad1) -> +bias -> ReLU
//   x:[32,64,112,112] f32 -> out same shape f32.
// sm_103-safe path (harness compiles PTX at compute_103: NO tcgen05):
//   mma.sync.m16n8k16 f16 implicit GEMM, register accumulators.
//   Single fp16 weight pass (K=576): activations are exact +-1 in fp16,
//   weight rounding gives rel_err ~1e-4 << 1e-3 gate.
// ============================================================================

#define N_IMG 32
#define HH    112
#define WW    112
#define HP    114
#define PIX   (HH*WW)            // 12544
#define NTILE 1568               // 32 n * 7 th * 7 tw  (16x16 px tiles)

#define B_BYTES    73728         // 9 taps * 4 ksteps * 4 jpairs * 32 lanes * 16B
#define HALO_BYTES 41472         // 18 rows * 18 px * 128B
#define OFF_B      0
#define OFF_H0     (OFF_B + B_BYTES)       // 73728
#define OFF_H1     (OFF_H0 + HALO_BYTES)   // 115200
#define OFF_MBAR   (OFF_H1 + HALO_BYTES)   // 156672
#define SMEM_TOTAL (OFF_MBAR + 16)         // 156688

// ---- scratch (device globals; no runtime allocation) ----
__device__ __align__(1024) __half g_xb[(size_t)N_IMG*HP*HP*64]; // 53.2MB
__device__ __align__(1024) unsigned char g_B[B_BYTES];
__device__ float2 g_part[64*32];
__device__ float2 g_ss[64];

// ============================ PTX helpers ===================================
static __device__ __forceinline__ uint32_t smem_u32(const void* p) {
    uint32_t a;
    asm("{ .reg .u64 t; cvta.to.shared.u64 t, %1; cvt.u32.u64 %0, t; }"
        : "=r"(a) : "l"(p));
    return a;
}

#define MBAR_INIT(mbar, cnt) \
    asm volatile("mbarrier.init.shared.b64 [%0], %1;" :: "r"(mbar), "r"(cnt) : "memory")

#define MBAR_EXPECT_TX(mbar, bytes) \
    asm volatile("mbarrier.arrive.expect_tx.shared.b64 _, [%0], %1;" \
                 :: "r"(mbar), "r"(bytes) : "memory")

#define MBAR_WAIT(mbar, ph) do {                                            \
    asm volatile("{\n\t.reg .pred P;\n\t"                                   \
        "WL%=:\n\t"                                                         \
        "mbarrier.try_wait.parity.acquire.cta.shared::cta.b64 P, [%0], %1, 0x989680;\n\t" \
        "@P bra.uni WD%=;\n\t"                                              \
        "bra.uni WL%=;\n\t"                                                 \
        "WD%=:\n\t}"                                                        \
        :: "r"(mbar), "r"((unsigned)(ph)) : "memory");                      \
} while (0)

#define BULK_G2S(dst, src, size, mbar) \
    asm volatile("cp.async.bulk.shared::cta.global.mbarrier::complete_tx::bytes [%0], [%1], %2, [%3];" \
                 :: "r"(dst), "l"(src), "r"(size), "r"(mbar) : "memory")

#define LDSM_X4(r, addr) \
    asm volatile("ldmatrix.sync.aligned.m8n8.x4.shared.b16 {%0,%1,%2,%3}, [%4];" \
        : "=r"((r)[0]),"=r"((r)[1]),"=r"((r)[2]),"=r"((r)[3]) : "r"(addr))

#define LDS128(v0,v1,v2,v3,addr) \
    asm volatile("ld.shared.v4.b32 {%0,%1,%2,%3}, [%4];" \
        : "=r"(v0),"=r"(v1),"=r"(v2),"=r"(v3) : "r"(addr))

#define MMA4(d, a, b0, b1) \
    asm volatile("mma.sync.aligned.m16n8k16.row.col.f32.f16.f16.f32 " \
        "{%0,%1,%2,%3}, {%4,%5,%6,%7}, {%8,%9}, {%0,%1,%2,%3};" \
        : "+f"((d)[0]),"+f"((d)[1]),"+f"((d)[2]),"+f"((d)[3]) \
        : "r"((a)[0]),"r"((a)[1]),"r"((a)[2]),"r"((a)[3]), "r"(b0),"r"(b1))

// ============================ pre-pass kernels ==============================

__global__ void k_stats(const float* __restrict__ x) {
    int c = blockIdx.x, n = blockIdx.y;
    const float* p = x + ((size_t)(n*64 + c)) * PIX;
    float s = 0.f, q = 0.f;
    for (int i = threadIdx.x; i < PIX; i += 256) { float v = p[i]; s += v; q += v*v; }
    __shared__ float rs[256], rq[256];
    rs[threadIdx.x] = s; rq[threadIdx.x] = q;
    __syncthreads();
    for (int o = 128; o > 0; o >>= 1) {
        if (threadIdx.x < o) { rs[threadIdx.x] += rs[threadIdx.x+o]; rq[threadIdx.x] += rq[threadIdx.x+o]; }
        __syncthreads();
    }
    if (threadIdx.x == 0) g_part[c*32 + n] = make_float2(rs[0], rq[0]);
}

__global__ void k_final(const float* __restrict__ gamma, const float* __restrict__ beta) {
    int c = threadIdx.x;
    if (c >= 64) return;
    float s = 0.f, q = 0.f;
    for (int n = 0; n < 32; n++) { float2 p = g_part[c*32 + n]; s += p.x; q += p.y; }
    const float inv = 1.0f / (float)(32*PIX);
    float mean = s * inv;
    float var  = q * inv - mean*mean;     // biased var, matches reference
    float sc = gamma[c] / sqrtf(var + 1e-4f);
    g_ss[c] = make_float2(sc, beta[c] - mean*sc);
}

// NCHW f32 -> padded NHWC fp16 sign with per-pixel 16B-chunk rotation
// (chunk position = chunk ^ (wp&7)) for conflict-free ldmatrix later.
__global__ void k_binarize(const float* __restrict__ x) {
    int hp = blockIdx.x, n = blockIdx.y;
    uint32_t* dst = (uint32_t*)(g_xb + ((size_t)(n*HP + hp)) * HP * 64); // rows of 32 u32
    if (hp == 0 || hp == HP-1) {
        for (int i = threadIdx.x; i < HP*32; i += 256) dst[i] = 0u;
        return;
    }
    __shared__ float s[64][113];
    __shared__ float2 ss[64];
    if (threadIdx.x < 64) ss[threadIdx.x] = g_ss[threadIdx.x];
    int h = hp - 1;
    const float* src = x + ((size_t)n*64) * PIX + (size_t)h * WW;
    for (int i = threadIdx.x; i < 64*WW; i += 256) {
        int c = i / WW, w = i % WW;
        s[c][w] = src[(size_t)c * PIX + w];
    }
    __syncthreads();
    if (threadIdx.x < 64) { // zero border columns wp=0, wp=113
        int cp = threadIdx.x & 31;
        int wp = (threadIdx.x < 32) ? 0 : (HP-1);
        dst[wp*32 + cp] = 0u;
    }
    for (int i = threadIdx.x; i < WW*32; i += 256) {
        int w = i >> 5, cp = i & 31, c = cp*2;
        float2 p0 = ss[c], p1 = ss[c+1];
        float v0 = s[c][w]   * p0.x + p0.y;
        float v1 = s[c+1][w] * p1.x + p1.y;
        uint32_t u0 = v0 > 0.f ? 0x3C00u : (v0 < 0.f ? 0xBC00u : 0u);  // fp16 +-1
        uint32_t u1 = v1 > 0.f ? 0x3C00u : (v1 < 0.f ? 0xBC00u : 0u);
        int wp = w + 1;
        int pos = (((cp>>2) ^ (wp & 7)) << 2) | (cp & 3);
        dst[wp*32 + pos] = u0 | (u1 << 16);
    }
}

// W [64o][64i][3][3] f32 -> fp16 B fragments for mma.m16n8k16 (row.col):
// layout g_B[ ((tap*4+kc)*4 + j)*512 + lane*16 ] = {nc=2j:u0,u1, nc=2j+1:u0,u1}
// b0,b1: k=tig*2,+1; b2,b3: k=tig*2+8,+9; n=nc*8+gid.
__global__ void k_wprep(const float* __restrict__ Wt) {
    int idx = blockIdx.x * 256 + threadIdx.x;
    if (idx >= 4608) return;
    int lane = idx & 31, j = (idx>>5)&3, kc = (idx>>7)&3, tap = idx>>9;
    int gid = lane >> 2, tig = lane & 3;
    uint32_t o4[4];
    #pragma unroll
    for (int s2 = 0; s2 < 2; s2++) {
        int n = (j*2 + s2)*8 + gid;
        #pragma unroll
        for (int p = 0; p < 2; p++) {
            uint32_t pr = 0;
            #pragma unroll
            for (int e = 0; e < 2; e++) {
                int kch = kc*16 + tig*2 + e + p*8;
                float w = Wt[((size_t)n*64 + kch)*9 + tap];
                __half v = __float2half(w);
                unsigned short us = *(unsigned short*)&v;
                pr |= (uint32_t)us << (e*16);
            }
            o4[s2*2 + p] = pr;
        }
    }
    *(uint4*)(g_B + (size_t)(((tap*4 + kc)*4 + j)*512) + (size_t)lane*16)
        = make_uint4(o4[0], o4[1], o4[2], o4[3]);
}

// ============================ conv kernel ===================================

static __device__ __forceinline__ void issue_halo(int tile, uint32_t dst, uint32_t mbar) {
    int nimg = tile / 49, r = tile % 49;
    int h0 = (r / 7) * 16, w0 = (r % 7) * 16;
    MBAR_EXPECT_TX(mbar, (unsigned)HALO_BYTES);
    const char* src = (const char*)g_xb + ((size_t)((nimg*HP + h0) * HP + w0)) * 128;
    #pragma unroll
    for (int rr = 0; rr < 18; rr++)
        BULK_G2S(dst + rr*2304, src + (size_t)rr * HP * 128, 2304u, mbar);
}

__global__ void __launch_bounds__(256, 1)
k_conv(const float* __restrict__ bias, float* __restrict__ out) {
    extern __shared__ char smem[];
    const uint32_t sb = smem_u32(smem);
    const int tid = threadIdx.x, wid = tid >> 5, L = tid & 31;
    const int wm = wid >> 1, nh = wid & 1;       // 4 M-groups x 2 N-halves
    const int gid = L >> 2, tig = L & 3;
    const int mx  = L & 15;                      // lane's ldmatrix row (pixel col)
    const int chi = L >> 4;                      // k 16B-chunk half

    // B fragments -> smem (linear copy; already fragment-packed)
    {
        const uint4* gb = (const uint4*)g_B;
        uint4* sB = (uint4*)smem;
        for (int i = tid; i < B_BYTES/16; i += 256) sB[i] = gb[i];
    }
    if (tid == 0) { MBAR_INIT(sb + OFF_MBAR, 1); MBAR_INIT(sb + OFF_MBAR + 8, 1); }
    __syncthreads();

    // bias in registers (2 consecutive out-channels per ncl)
    float bs[4][2];
    #pragma unroll
    for (int ncl = 0; ncl < 4; ncl++) {
        int n = (nh*4 + ncl)*8 + tig*2;
        bs[ncl][0] = bias[n]; bs[ncl][1] = bias[n+1];
    }

    if (tid == 0 && blockIdx.x < NTILE)
        issue_halo(blockIdx.x, sb + OFF_H0, sb + OFF_MBAR);

    int ph0 = 0, ph1 = 0;
    int it = 0;
    for (int tile = blockIdx.x; tile < NTILE; tile += gridDim.x, it++) {
        const int buf = it & 1;
        const int ntile = tile + gridDim.x;
        if (tid == 0 && ntile < NTILE)
            issue_halo(ntile, sb + (buf ? OFF_H0 : OFF_H1), sb + OFF_MBAR + (buf ^ 1)*8);

        if (buf == 0) { MBAR_WAIT(sb + OFF_MBAR,     ph0); ph0 ^= 1; }
        else          { MBAR_WAIT(sb + OFF_MBAR + 8, ph1); ph1 ^= 1; }
        const uint32_t hbase = sb + (buf ? OFF_H1 : OFF_H0);

        float acc[4][4][4];
        #pragma unroll
        for (int f = 0; f < 4; f++)
            #pragma unroll
            for (int c = 0; c < 4; c++)
                #pragma unroll
                for (int q = 0; q < 4; q++) acc[f][c][q] = 0.f;

        #pragma unroll 1
        for (int t = 0; t < 9; t++) {
            const int ky = t / 3, kx = t - ky*3;
            const int rk = (mx + kx) & 7;                 // rotation key
            const uint32_t rowbase = hbase
                + (uint32_t)(((wm*4 + ky)*18 + mx + kx) * 128);
            #pragma unroll
            for (int kc = 0; kc < 4; kc++) {
                const uint32_t col = (uint32_t)(((((kc<<1) | chi) ^ rk)) << 4);
                uint32_t a[4][4];
                #pragma unroll
                for (int f = 0; f < 4; f++)
                    LDSM_X4(a[f], rowbase + (uint32_t)(f*2304) + col);
                const uint32_t bb = sb
                    + (uint32_t)((((t*4 + kc)*4) + nh*2) * 512)
                    + (uint32_t)(L << 4);
                uint32_t b0x, b0y, b0z, b0w, b1x, b1y, b1z, b1w;
                LDS128(b0x, b0y, b0z, b0w, bb);
                LDS128(b1x, b1y, b1z, b1w, bb + 512);
                #pragma unroll
                for (int f = 0; f < 4; f++) {
                    MMA4(acc[f][0], a[f], b0x, b0y);
                    MMA4(acc[f][1], a[f], b0z, b0w);
                    MMA4(acc[f][2], a[f], b1x, b1y);
                    MMA4(acc[f][3], a[f], b1z, b1w);
                }
            }
        }
        __syncthreads();   // all warps done reading halo[buf] before its next refill

        // epilogue: bias + ReLU, direct stores (32B sectors along w)
        {
            const int nimg = tile / 49, r = tile % 49;
            const int h0 = (r / 7) * 16, w0 = (r % 7) * 16;
            #pragma unroll
            for (int f = 0; f < 4; f++) {
                const int h = h0 + wm*4 + f;
                #pragma unroll
                for (int ncl = 0; ncl < 4; ncl++) {
                    const int n = (nh*4 + ncl)*8 + tig*2;
                    float* p0 = out + ((size_t)(nimg*64 + n)) * PIX
                                    + (size_t)h * WW + w0;
                    float v0 = acc[f][ncl][0] + bs[ncl][0];
                    float v1 = acc[f][ncl][1] + bs[ncl][1];
                    float v2 = acc[f][ncl][2] + bs[ncl][0];
                    float v3 = acc[f][ncl][3] + bs[ncl][1];
                    p0[gid]           = v0 > 0.f ? v0 : 0.f;
                    p0[PIX + gid]     = v1 > 0.f ? v1 : 0.f;
                    p0[gid + 8]       = v2 > 0.f ? v2 : 0.f;
                    p0[PIX + gid + 8] = v3 > 0.f ? v3 : 0.f;
                }
            }
        }
    }
}

// ============================ launch ========================================
extern "C" void kernel_launch(void* const* d_in, const int* in_sizes, int n_in,
                              void* d_out, int out_size) {
    (void)in_sizes; (void)n_in; (void)out_size;
    const float* x     = (const float*)d_in[0];
    const float* gamma = (const float*)d_in[1];
    const float* beta  = (const float*)d_in[2];
    const float* Wt    = (const float*)d_in[3];
    const float* b     = (const float*)d_in[4];
    float* out = (float*)d_out;

    int sms = 148;
    cudaDeviceGetAttribute(&sms, cudaDevAttrMultiProcessorCount, 0);
    cudaFuncSetAttribute(k_conv, cudaFuncAttributeMaxDynamicSharedMemorySize, SMEM_TOTAL);

    k_stats<<<dim3(64, 32), 256>>>(x);
    k_final<<<1, 64>>>(gamma, beta);
    k_binarize<<<dim3(HP, N_IMG), 256>>>(x);
    k_wprep<<<(4608 + 255)/256, 256>>>(Wt);
    k_conv<<<sms, 256, SMEM_TOTAL>>>(b, out);
}